// round 16
// baseline (speedup 1.0000x reference)
#include <cuda_runtime.h>
#include <math.h>

#define B    32
#define C    3
#define H    512
#define W    512
#define TX   64               // output tile width
#define TY   32               // output tile height
#define RW   76               // res smem row stride (float4-aligned, 72 used)
#define RH   38               // res rows (TY + 6)
#define VW   73               // v1/v2 row stride (odd -> conflict-free column walks)
#define TILES_PER_IMG 128     // (512/64)*(512/32)

__device__ float g_psum  [B * TILES_PER_IMG];
__device__ float g_psumsq[B * TILES_PER_IMG];
__device__ float g_pS    [B * TILES_PER_IMG];

__global__ __launch_bounds__(256, 6)
void ldl_main(const float* __restrict__ net, const float* __restrict__ gt,
              float* __restrict__ out) {
    __shared__ float res[RH][RW];      // residual, col c <-> gx = 64*bx-4+c
    __shared__ float v1 [TY][VW];      // vertical 7-sums of r   (cols 1..70)
    __shared__ float v2 [TY][VW];      // vertical 7-sums of r^2
    __shared__ float red[3][8];

    const int bx  = blockIdx.x;        // 0..7
    const int by  = blockIdx.y;        // 0..15
    const int b   = blockIdx.z;
    const int tid = threadIdx.x;

    // zero the accumulator target for the batch kernel's atomicAdds
    if (bx == 0 && by == 0 && b == 0 && tid == 0) out[0] = 0.0f;

    const int x0a = TX * bx - 4;       // global x of smem col 0 (16B aligned)
    const int y0a = TY * by - 3;       // global y of smem row 0

    const int HW = H * W;
    const float* nb = net + b * (C * HW);
    const float* gb = gt  + b * (C * HW);

    const bool interior = (bx > 0) & (bx < 7) & (by > 0) & (by < 15);

    if (interior) {
        // ---- Phase 1 fast path: no bounds checks, no fixups ----
        for (int i = tid; i < RH * 18; i += 256) {
            int row = i / 18, v = i - row * 18;
            int p = (y0a + row) * W + x0a + 4 * v;
            float4 n0 = *(const float4*)(nb + p);
            float4 n1 = *(const float4*)(nb + p + HW);
            float4 n2 = *(const float4*)(nb + p + 2 * HW);
            float4 g0 = *(const float4*)(gb + p);
            float4 g1 = *(const float4*)(gb + p + HW);
            float4 g2 = *(const float4*)(gb + p + 2 * HW);
            float4 r;
            r.x = fabsf(g0.x - n0.x) + fabsf(g1.x - n1.x) + fabsf(g2.x - n2.x);
            r.y = fabsf(g0.y - n0.y) + fabsf(g1.y - n1.y) + fabsf(g2.y - n2.y);
            r.z = fabsf(g0.z - n0.z) + fabsf(g1.z - n1.z) + fabsf(g2.z - n2.z);
            r.w = fabsf(g0.w - n0.w) + fabsf(g1.w - n1.w) + fabsf(g2.w - n2.w);
            *(float4*)&res[row][4 * v] = r;
        }
        __syncthreads();
    } else {
        // ---- Phase 1: vectorized residual load (skip out-of-range vec4s) ----
        for (int i = tid; i < RH * 18; i += 256) {
            int row = i / 18, v = i - row * 18;
            int gy = y0a + row;
            int gx = x0a + 4 * v;      // multiple of 4 -> vec4 fully in or out
            if ((unsigned)gy < H && (unsigned)gx < W) {
                int p = gy * W + gx;
                float4 n0 = *(const float4*)(nb + p);
                float4 n1 = *(const float4*)(nb + p + HW);
                float4 n2 = *(const float4*)(nb + p + 2 * HW);
                float4 g0 = *(const float4*)(gb + p);
                float4 g1 = *(const float4*)(gb + p + HW);
                float4 g2 = *(const float4*)(gb + p + 2 * HW);
                float4 r;
                r.x = fabsf(g0.x - n0.x) + fabsf(g1.x - n1.x) + fabsf(g2.x - n2.x);
                r.y = fabsf(g0.y - n0.y) + fabsf(g1.y - n1.y) + fabsf(g2.y - n2.y);
                r.z = fabsf(g0.z - n0.z) + fabsf(g1.z - n1.z) + fabsf(g2.z - n2.z);
                r.w = fabsf(g0.w - n0.w) + fabsf(g1.w - n1.w) + fabsf(g2.w - n2.w);
                *(float4*)&res[row][4 * v] = r;
            }
        }
        __syncthreads();

        // ---- Phase 1b: reflect fixups (R13-proven, two syncs) ----
        if (by == 0) {                 // rows 0,1,2 <- rows 6,5,4
            for (int i = tid; i < 3 * 18; i += 256) {
                int r = i / 18, v = i - r * 18;
                *(float4*)&res[r][4 * v] = *(const float4*)&res[6 - r][4 * v];
            }
        }
        if (by == 15) {                // rows 35,36,37 <- rows 33,32,31
            for (int i = tid; i < 3 * 18; i += 256) {
                int r = 35 + i / 18, v = i % 18;
                *(float4*)&res[r][4 * v] = *(const float4*)&res[68 - r][4 * v];
            }
        }
        __syncthreads();
        if (bx == 0) {                 // cols 1,2,3 <- cols 7,6,5
            for (int i = tid; i < RH * 3; i += 256) {
                int r = i / 3, c = 1 + i % 3;
                res[r][c] = res[r][8 - c];
            }
        }
        if (bx == 7) {                 // cols 68,69,70 <- cols 66,65,64
            for (int i = tid; i < RH * 3; i += 256) {
                int r = i / 3, c = 68 + i % 3;
                res[r][c] = res[r][134 - c];   // gx' = 1022 - gx => c' = 134 - c
            }
        }
        __syncthreads();
    }

    // ---- Phase 2': vertical sliding 7-sum (read each res row ONCE) ----
    for (int t = tid; t < 280; t += 256) {
        int col = t % 70 + 1;          // 1..70
        int y0  = (t / 70) * 8;        // 0,8,16,24

        float w1[7], w2[7];
        float s1 = 0.f, s2 = 0.f;
        #pragma unroll
        for (int d = 0; d < 7; d++) {
            float v = res[y0 + d][col];
            w1[d] = v; w2[d] = v * v;
            s1 += w1[d]; s2 += w2[d];
        }
        v1[y0][col] = s1; v2[y0][col] = s2;
        #pragma unroll
        for (int j = 1; j < 8; j++) {
            float v = res[y0 + 6 + j][col];
            s1 += v - w1[j - 1];
            s2 += v * v - w2[j - 1];
            v1[y0 + j][col] = s1;
            v2[y0 + j][col] = s2;
        }
    }
    __syncthreads();

    // ---- Phase 3': horizontal sliding 7-sum, 8 outputs per thread ----
    const int w  = tid >> 5, l = tid & 31;
    const int y  = (w & 3) * 8 + (l >> 2);       // 0..31
    const int g  = (w >> 2) * 4 + (l & 3);       // 0..7
    const int cb = 1 + 8 * g;                    // first tap column

    float a1[7], a2[7];
    float s1 = 0.f, s2 = 0.f;
    #pragma unroll
    for (int d = 0; d < 7; d++) {
        a1[d] = v1[y][cb + d];
        a2[d] = v2[y][cb + d];
        s1 += a1[d]; s2 += a2[d];
    }
    // center pixels: 8 consecutive cols starting at 4+8g (16B-aligned:
    // row stride 304B, offset 16+32g) -> two conflict-free LDS.128
    // (per 8-lane phase, start banks {0,8,16,24,12,20,28,4} each spanning
    //  4 banks = full 32-bank coverage exactly once)
    float4 c0 = *(const float4*)&res[y + 3][4 + 8 * g];
    float4 c1 = *(const float4*)&res[y + 3][8 + 8 * g];
    float cen[8] = {c0.x, c0.y, c0.z, c0.w, c1.x, c1.y, c1.z, c1.w};

    float accS = 0.f, accSum = 0.f, accSq = 0.f;
    #pragma unroll
    for (int j = 0; j < 8; j++) {
        float pw = (s2 - s1 * s1 * (1.0f / 49.0f)) * (1.0f / 48.0f);
        accS   += fabsf(pw) * cen[j];
        accSum += cen[j];
        accSq  += cen[j] * cen[j];
        if (j < 7) {
            s1 += v1[y][cb + 7 + j] - a1[j];
            s2 += v2[y][cb + 7 + j] - a2[j];
        }
    }

    // ---- block reduction -> global partials ----
    #pragma unroll
    for (int off = 16; off; off >>= 1) {
        accS   += __shfl_down_sync(0xFFFFFFFFu, accS,   off);
        accSum += __shfl_down_sync(0xFFFFFFFFu, accSum, off);
        accSq  += __shfl_down_sync(0xFFFFFFFFu, accSq,  off);
    }
    if (l == 0) { red[0][w] = accS; red[1][w] = accSum; red[2][w] = accSq; }
    __syncthreads();
    if (tid == 0) {
        float S = 0.f, Su = 0.f, Sq = 0.f;
        #pragma unroll
        for (int k = 0; k < 8; k++) { S += red[0][k]; Su += red[1][k]; Sq += red[2][k]; }
        int tile = by * 8 + bx;
        g_pS    [b * TILES_PER_IMG + tile] = S;
        g_psum  [b * TILES_PER_IMG + tile] = Su;
        g_psumsq[b * TILES_PER_IMG + tile] = Sq;
    }
}

// One block per batch (32 blocks in parallel): reduce this batch's 128
// partials, compute powf(var, 0.2) * S_b, atomicAdd the scaled contribution.
__global__ __launch_bounds__(128)
void ldl_batch(float* __restrict__ out) {
    __shared__ double shS[4], shU[4], shQ[4];
    const int b   = blockIdx.x;
    const int tid = threadIdx.x;
    const int lane = tid & 31, wrp = tid >> 5;

    double S  = (double)g_pS    [b * TILES_PER_IMG + tid];
    double su = (double)g_psum  [b * TILES_PER_IMG + tid];
    double sq = (double)g_psumsq[b * TILES_PER_IMG + tid];

    #pragma unroll
    for (int off = 16; off; off >>= 1) {
        S  += __shfl_down_sync(0xFFFFFFFFu, S,  off);
        su += __shfl_down_sync(0xFFFFFFFFu, su, off);
        sq += __shfl_down_sync(0xFFFFFFFFu, sq, off);
    }
    if (lane == 0) { shS[wrp] = S; shU[wrp] = su; shQ[wrp] = sq; }
    __syncthreads();
    if (tid == 0) {
        double Sb = 0.0, sumr = 0.0, sumsq = 0.0;
        #pragma unroll
        for (int w = 0; w < 4; w++) { Sb += shS[w]; sumr += shU[w]; sumsq += shQ[w]; }
        const double N = (double)(H * W);
        double var = (sumsq - sumr * sumr / N) / (N - 1.0);
        if (var < 0.0) var = 0.0;
        float pw = powf((float)var, 0.2f);               // fp32 pow, err ~1e-7
        float contrib = (float)((double)pw * Sb / ((double)B * C * H * W));
        atomicAdd(out, contrib);
    }
}

extern "C" void kernel_launch(void* const* d_in, const int* in_sizes, int n_in,
                              void* d_out, int out_size) {
    const float* net = (const float*)d_in[0];   // net_output
    const float* gt  = (const float*)d_in[1];   // gt
    float* out = (float*)d_out;

    dim3 grid(W / TX, H / TY, B);               // 8 x 16 x 32
    ldl_main<<<grid, 256>>>(net, gt, out);
    ldl_batch<<<B, 128>>>(out);
}

// round 17
// speedup vs baseline: 1.3113x; 1.3113x over previous
#include <cuda_runtime.h>
#include <math.h>

#define B    32
#define C    3
#define H    512
#define W    512
#define TX   64               // output tile width
#define TY   32               // output tile height
#define RW   76               // res smem row stride (float4-aligned, 72 used)
#define RH   38               // res rows (TY + 6)
#define VW   73               // v1/v2 row stride (odd -> conflict-free column walks)
#define TILES_PER_IMG 128     // (512/64)*(512/32)

__device__ float g_psum  [B * TILES_PER_IMG];
__device__ float g_psumsq[B * TILES_PER_IMG];
__device__ float g_pS    [B * TILES_PER_IMG];

__global__ __launch_bounds__(256, 6)
void ldl_main(const float* __restrict__ net, const float* __restrict__ gt,
              float* __restrict__ out) {
    __shared__ float res[RH][RW];      // residual, col c <-> gx = 64*bx-4+c
    __shared__ float v1 [TY][VW];      // vertical 7-sums of r   (cols 1..70)
    __shared__ float v2 [TY][VW];      // vertical 7-sums of r^2
    __shared__ float red[3][8];

    const int bx  = blockIdx.x;        // 0..7
    const int by  = blockIdx.y;        // 0..15
    const int b   = blockIdx.z;
    const int tid = threadIdx.x;

    // zero the accumulator target for the batch kernel's atomicAdds
    if (bx == 0 && by == 0 && b == 0 && tid == 0) out[0] = 0.0f;

    const int x0a = TX * bx - 4;       // global x of smem col 0 (16B aligned)
    const int y0a = TY * by - 3;       // global y of smem row 0

    const int HW = H * W;
    const float* nb = net + b * (C * HW);
    const float* gb = gt  + b * (C * HW);

    // ---- Phase 1: vectorized residual load (skip out-of-range vec4s) ----
    for (int i = tid; i < RH * 18; i += 256) {
        int row = i / 18, v = i - row * 18;
        int gy = y0a + row;
        int gx = x0a + 4 * v;          // multiple of 4 -> vec4 fully in or out
        if ((unsigned)gy < H && (unsigned)gx < W) {
            int p = gy * W + gx;
            float4 n0 = *(const float4*)(nb + p);
            float4 n1 = *(const float4*)(nb + p + HW);
            float4 n2 = *(const float4*)(nb + p + 2 * HW);
            float4 g0 = *(const float4*)(gb + p);
            float4 g1 = *(const float4*)(gb + p + HW);
            float4 g2 = *(const float4*)(gb + p + 2 * HW);
            float4 r;
            r.x = fabsf(g0.x - n0.x) + fabsf(g1.x - n1.x) + fabsf(g2.x - n2.x);
            r.y = fabsf(g0.y - n0.y) + fabsf(g1.y - n1.y) + fabsf(g2.y - n2.y);
            r.z = fabsf(g0.z - n0.z) + fabsf(g1.z - n1.z) + fabsf(g2.z - n2.z);
            r.w = fabsf(g0.w - n0.w) + fabsf(g1.w - n1.w) + fabsf(g2.w - n2.w);
            *(float4*)&res[row][4 * v] = r;
        }
    }
    __syncthreads();

    // ---- Phase 1b: reflect fixups (sources always inside the tile) ----
    if (by == 0) {                     // rows 0,1,2 <- rows 6,5,4
        for (int i = tid; i < 3 * 18; i += 256) {
            int r = i / 18, v = i - r * 18;
            *(float4*)&res[r][4 * v] = *(const float4*)&res[6 - r][4 * v];
        }
    }
    if (by == 15) {                    // rows 35,36,37 <- rows 33,32,31
        for (int i = tid; i < 3 * 18; i += 256) {
            int r = 35 + i / 18, v = i % 18;
            *(float4*)&res[r][4 * v] = *(const float4*)&res[68 - r][4 * v];
        }
    }
    __syncthreads();
    if (bx == 0) {                     // cols 1,2,3 <- cols 7,6,5
        for (int i = tid; i < RH * 3; i += 256) {
            int r = i / 3, c = 1 + i % 3;
            res[r][c] = res[r][8 - c];
        }
    }
    if (bx == 7) {                     // cols 68,69,70 <- cols 66,65,64
        for (int i = tid; i < RH * 3; i += 256) {
            int r = i / 3, c = 68 + i % 3;
            res[r][c] = res[r][134 - c];   // gx' = 1022 - gx => c' = 134 - c
        }
    }
    __syncthreads();

    // ---- Phase 2': vertical sliding 7-sum (read each res row ONCE) ----
    for (int t = tid; t < 280; t += 256) {
        int col = t % 70 + 1;          // 1..70
        int y0  = (t / 70) * 8;        // 0,8,16,24

        float w1[7], w2[7];
        float s1 = 0.f, s2 = 0.f;
        #pragma unroll
        for (int d = 0; d < 7; d++) {
            float v = res[y0 + d][col];
            w1[d] = v; w2[d] = v * v;
            s1 += w1[d]; s2 += w2[d];
        }
        v1[y0][col] = s1; v2[y0][col] = s2;
        #pragma unroll
        for (int j = 1; j < 8; j++) {
            float v = res[y0 + 6 + j][col];
            s1 += v - w1[j - 1];
            s2 += v * v - w2[j - 1];
            v1[y0 + j][col] = s1;
            v2[y0 + j][col] = s2;
        }
    }
    __syncthreads();

    // ---- Phase 3': horizontal sliding 7-sum, 8 outputs per thread ----
    // Register-lean: no window arrays (slide subtrahends re-read from smem,
    // conflict-free: bank = 9q+8r injective mod 32), centers via two
    // sequential conflict-free LDS.128 (only 4 extra live floats at a time).
    const int w  = tid >> 5, l = tid & 31;
    const int y  = (w & 3) * 8 + (l >> 2);       // 0..31
    const int g  = (w >> 2) * 4 + (l & 3);       // 0..7
    const int cb = 1 + 8 * g;                    // first tap column

    float s1 = 0.f, s2 = 0.f;
    #pragma unroll
    for (int d = 0; d < 7; d++) {
        s1 += v1[y][cb + d];
        s2 += v2[y][cb + d];
    }
    float accS = 0.f, accSum = 0.f, accSq = 0.f;
    #pragma unroll
    for (int h = 0; h < 2; h++) {
        // 4 centers, 16B-aligned (row stride 304B, offset 16+32g+16h)
        float4 cq = *(const float4*)&res[y + 3][4 + 8 * g + 4 * h];
        float cen4[4] = {cq.x, cq.y, cq.z, cq.w};
        #pragma unroll
        for (int jj = 0; jj < 4; jj++) {
            int j = 4 * h + jj;
            float pw = (s2 - s1 * s1 * (1.0f / 49.0f)) * (1.0f / 48.0f);
            accS   += fabsf(pw) * cen4[jj];
            accSum += cen4[jj];
            accSq  += cen4[jj] * cen4[jj];
            if (j < 7) {
                s1 += v1[y][cb + 7 + j] - v1[y][cb + j];
                s2 += v2[y][cb + 7 + j] - v2[y][cb + j];
            }
        }
    }

    // ---- block reduction -> global partials ----
    #pragma unroll
    for (int off = 16; off; off >>= 1) {
        accS   += __shfl_down_sync(0xFFFFFFFFu, accS,   off);
        accSum += __shfl_down_sync(0xFFFFFFFFu, accSum, off);
        accSq  += __shfl_down_sync(0xFFFFFFFFu, accSq,  off);
    }
    if (l == 0) { red[0][w] = accS; red[1][w] = accSum; red[2][w] = accSq; }
    __syncthreads();
    if (tid == 0) {
        float S = 0.f, Su = 0.f, Sq = 0.f;
        #pragma unroll
        for (int k = 0; k < 8; k++) { S += red[0][k]; Su += red[1][k]; Sq += red[2][k]; }
        int tile = by * 8 + bx;
        g_pS    [b * TILES_PER_IMG + tile] = S;
        g_psum  [b * TILES_PER_IMG + tile] = Su;
        g_psumsq[b * TILES_PER_IMG + tile] = Sq;
    }
}

// One block per batch (32 blocks in parallel): reduce this batch's 128
// partials, compute powf(var, 0.2) * S_b, atomicAdd the scaled contribution.
__global__ __launch_bounds__(128)
void ldl_batch(float* __restrict__ out) {
    __shared__ double shS[4], shU[4], shQ[4];
    const int b   = blockIdx.x;
    const int tid = threadIdx.x;
    const int lane = tid & 31, wrp = tid >> 5;

    double S  = (double)g_pS    [b * TILES_PER_IMG + tid];
    double su = (double)g_psum  [b * TILES_PER_IMG + tid];
    double sq = (double)g_psumsq[b * TILES_PER_IMG + tid];

    #pragma unroll
    for (int off = 16; off; off >>= 1) {
        S  += __shfl_down_sync(0xFFFFFFFFu, S,  off);
        su += __shfl_down_sync(0xFFFFFFFFu, su, off);
        sq += __shfl_down_sync(0xFFFFFFFFu, sq, off);
    }
    if (lane == 0) { shS[wrp] = S; shU[wrp] = su; shQ[wrp] = sq; }
    __syncthreads();
    if (tid == 0) {
        double Sb = 0.0, sumr = 0.0, sumsq = 0.0;
        #pragma unroll
        for (int w = 0; w < 4; w++) { Sb += shS[w]; sumr += shU[w]; sumsq += shQ[w]; }
        const double N = (double)(H * W);
        double var = (sumsq - sumr * sumr / N) / (N - 1.0);
        if (var < 0.0) var = 0.0;
        float pw = powf((float)var, 0.2f);               // fp32 pow, err ~1e-7
        float contrib = (float)((double)pw * Sb / ((double)B * C * H * W));
        atomicAdd(out, contrib);
    }
}

extern "C" void kernel_launch(void* const* d_in, const int* in_sizes, int n_in,
                              void* d_out, int out_size) {
    const float* net = (const float*)d_in[0];   // net_output
    const float* gt  = (const float*)d_in[1];   // gt
    float* out = (float*)d_out;

    dim3 grid(W / TX, H / TY, B);               // 8 x 16 x 32
    ldl_main<<<grid, 256>>>(net, gt, out);
    ldl_batch<<<B, 128>>>(out);
}